// round 1
// baseline (speedup 1.0000x reference)
#include <cuda_runtime.h>
#include <math.h>

// Problem constants
#define BL   4096   // BSZ*L tokens
#define DD   1024   // model dim
#define HH   16     // heads (SSM state)
#define OO   1024   // output dim of C/D
#define FF   4096   // FFN hidden
#define LSEQ 1024
#define BSZN 4

// Scratch (device globals; no allocations allowed)
__device__ float g_xln[BL * DD];   // LN1 output
__device__ float g_Bg [BL * HH];   // gated B
__device__ float g_hs [BL * HH];   // scan states
__device__ float g_y  [BL * DD];   // pre-LN2 residual stream
__device__ float g_x3 [BL * DD];   // LN2 output
__device__ float g_t  [BL * FF];   // FFN hidden

// ---------------------------------------------------------------------------
// LayerNorm: one block (256 thr) per row of 1024
// mode 0: src param -> g_xln (g1/be1); mode 1: g_y -> g_x3 (g2/be2)
// ---------------------------------------------------------------------------
__global__ void ln_kernel(const float* __restrict__ src,
                          const float* __restrict__ gw,
                          const float* __restrict__ bw, int mode) {
    int row = blockIdx.x;
    int tid = threadIdx.x;
    const float* x = (mode == 0 ? src : g_y) + (size_t)row * DD;
    float* dst = (mode == 0 ? g_xln : g_x3) + (size_t)row * DD;

    float v[4];
    float s = 0.f, s2 = 0.f;
#pragma unroll
    for (int i = 0; i < 4; i++) {
        v[i] = x[tid + 256 * i];
        s += v[i];
        s2 += v[i] * v[i];
    }
#pragma unroll
    for (int o = 16; o > 0; o >>= 1) {
        s  += __shfl_down_sync(0xffffffffu, s,  o);
        s2 += __shfl_down_sync(0xffffffffu, s2, o);
    }
    __shared__ float rs[8], rs2[8], stats[2];
    int warp = tid >> 5, lane = tid & 31;
    if (lane == 0) { rs[warp] = s; rs2[warp] = s2; }
    __syncthreads();
    if (tid == 0) {
        float a = 0.f, b = 0.f;
#pragma unroll
        for (int i = 0; i < 8; i++) { a += rs[i]; b += rs2[i]; }
        float mean = a * (1.0f / DD);
        float var  = b * (1.0f / DD) - mean * mean;
        stats[0] = mean;
        stats[1] = rsqrtf(var + 1e-5f);
    }
    __syncthreads();
    float mean = stats[0], rstd = stats[1];
#pragma unroll
    for (int i = 0; i < 4; i++) {
        int c = tid + 256 * i;
        dst[c] = (v[i] - mean) * rstd * gw[c] + bw[c];
    }
}

// ---------------------------------------------------------------------------
// B projection + gate: Bg = (x@Wb.T + bb) * sigmoid(x@Wbg.T + bbg)
// block per row; 8 warps, each warp does 2 heads
// ---------------------------------------------------------------------------
__global__ void projB_kernel(const float* __restrict__ Wb,
                             const float* __restrict__ bb,
                             const float* __restrict__ Wbg,
                             const float* __restrict__ bbg) {
    int row = blockIdx.x;
    int warp = threadIdx.x >> 5, lane = threadIdx.x & 31;
    const float* x = g_xln + (size_t)row * DD;
    for (int h = warp; h < HH; h += 8) {
        const float* wb = Wb  + (size_t)h * DD;
        const float* wg = Wbg + (size_t)h * DD;
        float sb = 0.f, sg = 0.f;
        for (int k = lane; k < DD; k += 32) {
            float xv = x[k];
            sb += xv * wb[k];
            sg += xv * wg[k];
        }
#pragma unroll
        for (int o = 16; o > 0; o >>= 1) {
            sb += __shfl_down_sync(0xffffffffu, sb, o);
            sg += __shfl_down_sync(0xffffffffu, sg, o);
        }
        if (lane == 0) {
            float bval = sb + bb[h];
            float gval = sg + bbg[h];
            g_Bg[(size_t)row * HH + h] = bval * (1.f / (1.f + expf(-gval)));
        }
    }
}

// ---------------------------------------------------------------------------
// Selective scan: 64 independent (b,h) chains, serial over L.
// Emits per-step states g_hs and final state -> last_h output.
// ---------------------------------------------------------------------------
__global__ void scan_kernel(const float* __restrict__ h0,
                            const float* __restrict__ A,
                            float* __restrict__ lasth, int write_last) {
    int t = threadIdx.x;
    if (t >= BSZN * HH) return;
    int b = t / HH, h = t % HH;
    float dA = expf(A[h]);
    float hc = h0[b * HH + h];
    const float* bp = g_Bg + (size_t)b * LSEQ * HH + h;
    float* hp = g_hs + (size_t)b * LSEQ * HH + h;
#pragma unroll 4
    for (int l = 0; l < LSEQ; l++) {
        hc = dA * hc + bp[(size_t)l * HH];
        hp[(size_t)l * HH] = hc;
    }
    if (write_last) lasth[b * HH + h] = hc;
}

// ---------------------------------------------------------------------------
// Fused: ssm[m,o] = sum_h hs[m,h]*(x@Wc_h.T+bc_h)*sigmoid(x@Wcg_h.T+bcg_h)
//                 + (x@Wd.T + bd)
//        y[m,o]  = batch_vectors[m,o] + ssm[m,o]
// Tile: BM=128 x BN=64, BK=16; 256 thr; microtile 8x4.
// ---------------------------------------------------------------------------
#define BM4 128
#define BN4 64
#define BK4 16

__global__ __launch_bounds__(256, 1) void fused_ssm_kernel(
    const float* __restrict__ Wc,  const float* __restrict__ bc,
    const float* __restrict__ Wcg, const float* __restrict__ bcg,
    const float* __restrict__ Wd,  const float* __restrict__ bd,
    const float* __restrict__ bv) {
    __shared__ float xs [BK4][BM4 + 4];
    __shared__ float wcs[BK4][BN4 + 4];
    __shared__ float wgs[BK4][BN4 + 4];

    int tid = threadIdx.x;
    int tx = tid & 15, ty = tid >> 4;
    int mBase = blockIdx.y * BM4;
    int nBase = blockIdx.x * BN4;
    int m0 = ty * 8, n0 = tx * 4;

    int l_r = tid >> 2;           // row within tile for loads
    int l_k = (tid & 3) * 4;      // k offset (float4)

    float ssm[8][4];
#pragma unroll
    for (int i = 0; i < 8; i++)
#pragma unroll
        for (int j = 0; j < 4; j++) ssm[i][j] = 0.f;

    // ---- 16 gated head passes ----
    for (int h = 0; h < HH; ++h) {
        const float* Wc_h = Wc  + (size_t)h * OO * DD;
        const float* Wg_h = Wcg + (size_t)h * OO * DD;
        float acc_c[8][4], acc_g[8][4];
#pragma unroll
        for (int i = 0; i < 8; i++)
#pragma unroll
            for (int j = 0; j < 4; j++) { acc_c[i][j] = 0.f; acc_g[i][j] = 0.f; }

        for (int k0 = 0; k0 < DD; k0 += BK4) {
#pragma unroll
            for (int it = 0; it < 2; ++it) {
                int m = l_r + it * 64;
                float4 v = *reinterpret_cast<const float4*>(
                    &g_xln[(size_t)(mBase + m) * DD + k0 + l_k]);
                xs[l_k + 0][m] = v.x; xs[l_k + 1][m] = v.y;
                xs[l_k + 2][m] = v.z; xs[l_k + 3][m] = v.w;
            }
            {
                float4 v = *reinterpret_cast<const float4*>(
                    &Wc_h[(size_t)(nBase + l_r) * DD + k0 + l_k]);
                wcs[l_k + 0][l_r] = v.x; wcs[l_k + 1][l_r] = v.y;
                wcs[l_k + 2][l_r] = v.z; wcs[l_k + 3][l_r] = v.w;
            }
            {
                float4 v = *reinterpret_cast<const float4*>(
                    &Wg_h[(size_t)(nBase + l_r) * DD + k0 + l_k]);
                wgs[l_k + 0][l_r] = v.x; wgs[l_k + 1][l_r] = v.y;
                wgs[l_k + 2][l_r] = v.z; wgs[l_k + 3][l_r] = v.w;
            }
            __syncthreads();
#pragma unroll
            for (int kk = 0; kk < BK4; ++kk) {
                float a[8], pc[4], pg[4];
#pragma unroll
                for (int i = 0; i < 8; i++) a[i] = xs[kk][m0 + i];
#pragma unroll
                for (int j = 0; j < 4; j++) { pc[j] = wcs[kk][n0 + j]; pg[j] = wgs[kk][n0 + j]; }
#pragma unroll
                for (int i = 0; i < 8; i++)
#pragma unroll
                    for (int j = 0; j < 4; j++) {
                        acc_c[i][j] += a[i] * pc[j];
                        acc_g[i][j] += a[i] * pg[j];
                    }
            }
            __syncthreads();
        }
        // epilogue: gate, scale by hs, accumulate
        float hsv[8];
#pragma unroll
        for (int i = 0; i < 8; i++)
            hsv[i] = g_hs[(size_t)(mBase + m0 + i) * HH + h];
#pragma unroll
        for (int j = 0; j < 4; j++) {
            int n = nBase + n0 + j;
            float bcv = bc [h * OO + n];
            float bgv = bcg[h * OO + n];
#pragma unroll
            for (int i = 0; i < 8; i++) {
                float c  = acc_c[i][j] + bcv;
                float gv = acc_g[i][j] + bgv;
                ssm[i][j] += hsv[i] * c * (1.f / (1.f + __expf(-gv)));
            }
        }
    }

    // ---- Wd pass (ungated) ----
    {
        float acc_c[8][4];
#pragma unroll
        for (int i = 0; i < 8; i++)
#pragma unroll
            for (int j = 0; j < 4; j++) acc_c[i][j] = 0.f;

        for (int k0 = 0; k0 < DD; k0 += BK4) {
#pragma unroll
            for (int it = 0; it < 2; ++it) {
                int m = l_r + it * 64;
                float4 v = *reinterpret_cast<const float4*>(
                    &g_xln[(size_t)(mBase + m) * DD + k0 + l_k]);
                xs[l_k + 0][m] = v.x; xs[l_k + 1][m] = v.y;
                xs[l_k + 2][m] = v.z; xs[l_k + 3][m] = v.w;
            }
            {
                float4 v = *reinterpret_cast<const float4*>(
                    &Wd[(size_t)(nBase + l_r) * DD + k0 + l_k]);
                wcs[l_k + 0][l_r] = v.x; wcs[l_k + 1][l_r] = v.y;
                wcs[l_k + 2][l_r] = v.z; wcs[l_k + 3][l_r] = v.w;
            }
            __syncthreads();
#pragma unroll
            for (int kk = 0; kk < BK4; ++kk) {
                float a[8], pc[4];
#pragma unroll
                for (int i = 0; i < 8; i++) a[i] = xs[kk][m0 + i];
#pragma unroll
                for (int j = 0; j < 4; j++) pc[j] = wcs[kk][n0 + j];
#pragma unroll
                for (int i = 0; i < 8; i++)
#pragma unroll
                    for (int j = 0; j < 4; j++) acc_c[i][j] += a[i] * pc[j];
            }
            __syncthreads();
        }
#pragma unroll
        for (int j = 0; j < 4; j++) {
            int n = nBase + n0 + j;
            float bdv = bd[n];
#pragma unroll
            for (int i = 0; i < 8; i++) ssm[i][j] += acc_c[i][j] + bdv;
        }
    }

    // y = batch_vectors + ssm
#pragma unroll
    for (int i = 0; i < 8; i++) {
        size_t m = (size_t)(mBase + m0 + i);
#pragma unroll
        for (int j = 0; j < 4; j++) {
            int n = nBase + n0 + j;
            g_y[m * OO + n] = bv[m * OO + n] + ssm[i][j];
        }
    }
}

// ---------------------------------------------------------------------------
// FFN GEMM1 + exact GeLU: g_t = gelu(g_x3 @ W1.T + b1)  (4096x4096x1024)
// BM=BN=128, BK=16, 256 thr, 8x8 micro.
// ---------------------------------------------------------------------------
__global__ __launch_bounds__(256, 1) void gemm1_gelu_kernel(
    const float* __restrict__ W1, const float* __restrict__ b1) {
    __shared__ float xs[16][132];
    __shared__ float ws[16][132];
    int tid = threadIdx.x;
    int tx = tid & 15, ty = tid >> 4;
    int mBase = blockIdx.y * 128, nBase = blockIdx.x * 128;
    int m0 = ty * 8, n0 = tx * 8;
    int l_r = tid >> 2;
    int l_k = (tid & 3) * 4;

    float acc[8][8];
#pragma unroll
    for (int i = 0; i < 8; i++)
#pragma unroll
        for (int j = 0; j < 8; j++) acc[i][j] = 0.f;

    for (int k0 = 0; k0 < DD; k0 += 16) {
#pragma unroll
        for (int it = 0; it < 2; ++it) {
            int m = l_r + it * 64;
            float4 v = *reinterpret_cast<const float4*>(
                &g_x3[(size_t)(mBase + m) * DD + k0 + l_k]);
            xs[l_k + 0][m] = v.x; xs[l_k + 1][m] = v.y;
            xs[l_k + 2][m] = v.z; xs[l_k + 3][m] = v.w;
        }
#pragma unroll
        for (int it = 0; it < 2; ++it) {
            int n = l_r + it * 64;
            float4 v = *reinterpret_cast<const float4*>(
                &W1[(size_t)(nBase + n) * DD + k0 + l_k]);
            ws[l_k + 0][n] = v.x; ws[l_k + 1][n] = v.y;
            ws[l_k + 2][n] = v.z; ws[l_k + 3][n] = v.w;
        }
        __syncthreads();
#pragma unroll
        for (int kk = 0; kk < 16; ++kk) {
            float a[8], b[8];
#pragma unroll
            for (int i = 0; i < 8; i++) a[i] = xs[kk][m0 + i];
#pragma unroll
            for (int j = 0; j < 8; j++) b[j] = ws[kk][n0 + j];
#pragma unroll
            for (int i = 0; i < 8; i++)
#pragma unroll
                for (int j = 0; j < 8; j++) acc[i][j] += a[i] * b[j];
        }
        __syncthreads();
    }
#pragma unroll
    for (int i = 0; i < 8; i++) {
        size_t m = (size_t)(mBase + m0 + i);
#pragma unroll
        for (int j = 0; j < 8; j++) {
            int n = nBase + n0 + j;
            float v = acc[i][j] + b1[n];
            g_t[m * FF + n] = 0.5f * v * (1.0f + erff(v * 0.70710678118654752f));
        }
    }
}

// ---------------------------------------------------------------------------
// FFN GEMM2 + residual: out = g_x3 + g_t @ W2.T + b2  (4096x1024x4096)
// ---------------------------------------------------------------------------
__global__ __launch_bounds__(256, 1) void gemm2_out_kernel(
    const float* __restrict__ W2, const float* __restrict__ b2,
    float* __restrict__ out) {
    __shared__ float xs[16][132];
    __shared__ float ws[16][132];
    int tid = threadIdx.x;
    int tx = tid & 15, ty = tid >> 4;
    int mBase = blockIdx.y * 128, nBase = blockIdx.x * 128;
    int m0 = ty * 8, n0 = tx * 8;
    int l_r = tid >> 2;
    int l_k = (tid & 3) * 4;

    float acc[8][8];
#pragma unroll
    for (int i = 0; i < 8; i++)
#pragma unroll
        for (int j = 0; j < 8; j++) acc[i][j] = 0.f;

    for (int k0 = 0; k0 < FF; k0 += 16) {
#pragma unroll
        for (int it = 0; it < 2; ++it) {
            int m = l_r + it * 64;
            float4 v = *reinterpret_cast<const float4*>(
                &g_t[(size_t)(mBase + m) * FF + k0 + l_k]);
            xs[l_k + 0][m] = v.x; xs[l_k + 1][m] = v.y;
            xs[l_k + 2][m] = v.z; xs[l_k + 3][m] = v.w;
        }
#pragma unroll
        for (int it = 0; it < 2; ++it) {
            int n = l_r + it * 64;
            float4 v = *reinterpret_cast<const float4*>(
                &W2[(size_t)(nBase + n) * FF + k0 + l_k]);
            ws[l_k + 0][n] = v.x; ws[l_k + 1][n] = v.y;
            ws[l_k + 2][n] = v.z; ws[l_k + 3][n] = v.w;
        }
        __syncthreads();
#pragma unroll
        for (int kk = 0; kk < 16; ++kk) {
            float a[8], b[8];
#pragma unroll
            for (int i = 0; i < 8; i++) a[i] = xs[kk][m0 + i];
#pragma unroll
            for (int j = 0; j < 8; j++) b[j] = ws[kk][n0 + j];
#pragma unroll
            for (int i = 0; i < 8; i++)
#pragma unroll
                for (int j = 0; j < 8; j++) acc[i][j] += a[i] * b[j];
        }
        __syncthreads();
    }
#pragma unroll
    for (int i = 0; i < 8; i++) {
        size_t m = (size_t)(mBase + m0 + i);
#pragma unroll
        for (int j = 0; j < 8; j++) {
            int n = nBase + n0 + j;
            out[m * DD + n] = g_x3[m * DD + n] + acc[i][j] + b2[n];
        }
    }
}

// ---------------------------------------------------------------------------
extern "C" void kernel_launch(void* const* d_in, const int* in_sizes, int n_in,
                              void* d_out, int out_size) {
    const float* bv  = (const float*)d_in[0];
    const float* h0  = (const float*)d_in[1];
    const float* A   = (const float*)d_in[2];
    const float* Wb  = (const float*)d_in[3];
    const float* bb  = (const float*)d_in[4];
    const float* Wc  = (const float*)d_in[5];
    const float* bc  = (const float*)d_in[6];
    const float* Wd  = (const float*)d_in[7];
    const float* bd  = (const float*)d_in[8];
    const float* Wbg = (const float*)d_in[9];
    const float* bbg = (const float*)d_in[10];
    const float* Wcg = (const float*)d_in[11];
    const float* bcg = (const float*)d_in[12];
    const float* W1  = (const float*)d_in[13];
    const float* b1  = (const float*)d_in[14];
    const float* W2  = (const float*)d_in[15];
    const float* b2  = (const float*)d_in[16];
    const float* g1  = (const float*)d_in[17];
    const float* be1 = (const float*)d_in[18];
    const float* g2  = (const float*)d_in[19];
    const float* be2 = (const float*)d_in[20];

    float* out = (float*)d_out;
    const int X_ELEMS = BL * DD;            // 4194304
    int write_last = (out_size >= X_ELEMS + BSZN * HH) ? 1 : 0;
    float* lasth = out + X_ELEMS;           // last_h right after x

    // 1) LN1
    ln_kernel<<<BL, 256>>>(bv, g1, be1, 0);
    // 2) B projection + gate
    projB_kernel<<<BL, 256>>>(Wb, bb, Wbg, bbg);
    // 3) selective scan (+ last_h)
    scan_kernel<<<1, 64>>>(h0, A, lasth, write_last);
    // 4) fused dual-GEMM gate + hs-contraction + Wd + residual
    {
        dim3 grid(OO / BN4, BL / BM4);      // (16, 32)
        fused_ssm_kernel<<<grid, 256>>>(Wc, bc, Wcg, bcg, Wd, bd, bv);
    }
    // 5) LN2
    ln_kernel<<<BL, 256>>>(bv, g2, be2, 1);
    // 6) FFN GEMM1 + GeLU
    {
        dim3 grid(FF / 128, BL / 128);      // (32, 32)
        gemm1_gelu_kernel<<<grid, 256>>>(W1, b1);
    }
    // 7) FFN GEMM2 + residual -> out
    {
        dim3 grid(DD / 128, BL / 128);      // (8, 32)
        gemm2_out_kernel<<<grid, 256>>>(W2, b2, out);
    }
}

// round 2
// speedup vs baseline: 3.7383x; 3.7383x over previous
#include <cuda_runtime.h>
#include <math.h>
#include <stdint.h>

#define BL   4096
#define DD   1024
#define HH   16
#define OO   1024
#define FF   4096
#define LSEQ 1024
#define BSZN 4

// ---------------- scratch (device globals; no allocation allowed) ----------
__device__ float g_xln [BL * DD];     // LN1 out fp32 (for projB)
__device__ float g_xlnt[BL * DD];     // LN1 out tf32-rounded (GEMM A)
__device__ float g_Bg  [BL * HH];
__device__ float g_hs  [BL * HH];
__device__ float g_y   [BL * DD];     // pre-LN2 residual
__device__ float g_x3  [BL * DD];     // LN2 out fp32 (final residual)
__device__ float g_x3t [BL * DD];     // LN2 out rounded (GEMM A)
__device__ float g_t   [BL * FF];     // gelu out, rounded (GEMM A)
__device__ float g_Wc_t [HH * OO * DD];
__device__ float g_Wcg_t[HH * OO * DD];
__device__ float g_Wd_t [OO * DD];
__device__ float g_W1_t [FF * DD];
__device__ float g_W2_t [DD * FF];

// ---------------- helpers ---------------------------------------------------
__device__ __forceinline__ float tf32r(float f) {
    uint32_t u;
    asm("cvt.rna.tf32.f32 %0, %1;" : "=r"(u) : "f"(f));
    return __uint_as_float(u);
}
__device__ __forceinline__ void mma8(float* c, const uint32_t* a, const uint32_t* b) {
    asm volatile(
        "mma.sync.aligned.m16n8k8.row.col.f32.tf32.tf32.f32 "
        "{%0,%1,%2,%3},{%4,%5,%6,%7},{%8,%9},{%0,%1,%2,%3};"
        : "+f"(c[0]), "+f"(c[1]), "+f"(c[2]), "+f"(c[3])
        : "r"(a[0]), "r"(a[1]), "r"(a[2]), "r"(a[3]), "r"(b[0]), "r"(b[1]));
}
__device__ __forceinline__ void cp16(uint32_t s, const float* gp) {
    asm volatile("cp.async.cg.shared.global [%0], [%1], 16;" :: "r"(s), "l"(gp));
}
__device__ __forceinline__ void cp_commit() { asm volatile("cp.async.commit_group;"); }
__device__ __forceinline__ void cp_wait0()  { asm volatile("cp.async.wait_group 0;"); }
__device__ __forceinline__ float sigm(float x) { return 1.f / (1.f + __expf(-x)); }

// ---------------- tf32 rounding conversion ---------------------------------
__global__ void cvt_kernel(const float* __restrict__ src, int which, int n4) {
    int i = blockIdx.x * blockDim.x + threadIdx.x;
    if (i >= n4) return;
    float4 v = ((const float4*)src)[i];
    v.x = tf32r(v.x); v.y = tf32r(v.y); v.z = tf32r(v.z); v.w = tf32r(v.w);
    float4* dst;
    switch (which) {
        case 0: dst = (float4*)g_Wc_t;  break;
        case 1: dst = (float4*)g_Wcg_t; break;
        case 2: dst = (float4*)g_Wd_t;  break;
        case 3: dst = (float4*)g_W1_t;  break;
        default: dst = (float4*)g_W2_t; break;
    }
    dst[i] = v;
}

// ---------------- LayerNorm (writes fp32 + rounded copies) -----------------
__global__ void ln_kernel(const float* __restrict__ src,
                          const float* __restrict__ gw,
                          const float* __restrict__ bw, int mode) {
    int row = blockIdx.x;
    int tid = threadIdx.x;
    const float* x = (mode == 0 ? src : g_y) + (size_t)row * DD;
    float* dst  = (mode == 0 ? g_xln  : g_x3)  + (size_t)row * DD;
    float* dstt = (mode == 0 ? g_xlnt : g_x3t) + (size_t)row * DD;

    float v[4];
    float s = 0.f, s2 = 0.f;
#pragma unroll
    for (int i = 0; i < 4; i++) {
        v[i] = x[tid + 256 * i];
        s += v[i]; s2 += v[i] * v[i];
    }
#pragma unroll
    for (int o = 16; o > 0; o >>= 1) {
        s  += __shfl_down_sync(0xffffffffu, s,  o);
        s2 += __shfl_down_sync(0xffffffffu, s2, o);
    }
    __shared__ float rs[8], rs2[8], stats[2];
    int warp = tid >> 5, lane = tid & 31;
    if (lane == 0) { rs[warp] = s; rs2[warp] = s2; }
    __syncthreads();
    if (tid == 0) {
        float a = 0.f, b = 0.f;
#pragma unroll
        for (int i = 0; i < 8; i++) { a += rs[i]; b += rs2[i]; }
        float mean = a * (1.0f / DD);
        float var  = b * (1.0f / DD) - mean * mean;
        stats[0] = mean; stats[1] = rsqrtf(var + 1e-5f);
    }
    __syncthreads();
    float mean = stats[0], rstd = stats[1];
#pragma unroll
    for (int i = 0; i < 4; i++) {
        int c = tid + 256 * i;
        float o = (v[i] - mean) * rstd * gw[c] + bw[c];
        dst[c]  = o;
        dstt[c] = tf32r(o);
    }
}

// ---------------- B projection + gate (fp32, exact path for last_h) --------
__global__ void projB_kernel(const float* __restrict__ Wb,
                             const float* __restrict__ bb,
                             const float* __restrict__ Wbg,
                             const float* __restrict__ bbg) {
    int row = blockIdx.x;
    int warp = threadIdx.x >> 5, lane = threadIdx.x & 31;
    const float* x = g_xln + (size_t)row * DD;
    for (int h = warp; h < HH; h += 8) {
        const float* wb = Wb  + (size_t)h * DD;
        const float* wg = Wbg + (size_t)h * DD;
        float sb = 0.f, sg = 0.f;
        for (int k = lane; k < DD; k += 32) {
            float xv = x[k];
            sb += xv * wb[k];
            sg += xv * wg[k];
        }
#pragma unroll
        for (int o = 16; o > 0; o >>= 1) {
            sb += __shfl_down_sync(0xffffffffu, sb, o);
            sg += __shfl_down_sync(0xffffffffu, sg, o);
        }
        if (lane == 0) {
            float bval = sb + bb[h];
            float gval = sg + bbg[h];
            g_Bg[(size_t)row * HH + h] = bval * (1.f / (1.f + expf(-gval)));
        }
    }
}

// ---------------- selective scan --------------------------------------------
__global__ void scan_kernel(const float* __restrict__ h0,
                            const float* __restrict__ A,
                            float* __restrict__ lasth, int write_last) {
    int tt = threadIdx.x;
    if (tt >= BSZN * HH) return;
    int b = tt / HH, h = tt % HH;
    float dA = expf(A[h]);
    float hc = h0[b * HH + h];
    const float* bp = g_Bg + (size_t)b * LSEQ * HH + h;
    float* hp = g_hs + (size_t)b * LSEQ * HH + h;
#pragma unroll 4
    for (int l = 0; l < LSEQ; l++) {
        hc = dA * hc + bp[(size_t)l * HH];
        hp[(size_t)l * HH] = hc;
    }
    if (write_last) lasth[b * HH + h] = hc;
}

// ============================================================================
// Fused SSM kernel (tf32 tensor cores)
// Block: 128 (M) x 128 (N), 256 thr, warp grid 2(M)x4(N), warp tile 64x32.
// Loops 16 heads (dual GEMM: Wc & Wcg) + 1 Wd pass; ssm accumulated in smem.
// ============================================================================
#define TSTR 36            // smem row stride (32 + 4 pad): banks 4g+t, conflict-free
#define STAGE_F (128 * TSTR)

template <bool DUAL>
__device__ __forceinline__ void gemm_pass(
    const float* __restrict__ W0, const float* __restrict__ W1p,
    const float* sX, const float* sWc, const float* sWg,
    uint32_t sXu, uint32_t sWcu, uint32_t sWgu,
    int tid, int g, int t, int wm, int wn, int mBase, int nBase,
    float (*accC)[4][4], float (*accG)[4][4])
{
    auto issue = [&](int kc, int st) {
        int k0 = kc * 32;
#pragma unroll
        for (int i = 0; i < 4; i++) {
            int j = tid + i * 256; int row = j >> 3; int c = (j & 7) * 4;
            cp16(sXu + (uint32_t)(((st * 128 + row) * TSTR) + c) * 4,
                 &g_xlnt[(size_t)(mBase + row) * DD + k0 + c]);
        }
#pragma unroll
        for (int i = 0; i < 4; i++) {
            int j = tid + i * 256; int row = j >> 3; int c = (j & 7) * 4;
            cp16(sWcu + (uint32_t)(((st * 128 + row) * TSTR) + c) * 4,
                 &W0[(size_t)(nBase + row) * DD + k0 + c]);
        }
        if (DUAL) {
#pragma unroll
            for (int i = 0; i < 4; i++) {
                int j = tid + i * 256; int row = j >> 3; int c = (j & 7) * 4;
                cp16(sWgu + (uint32_t)(((st * 128 + row) * TSTR) + c) * 4,
                     &W1p[(size_t)(nBase + row) * DD + k0 + c]);
            }
        }
        cp_commit();
    };

    issue(0, 0);
#pragma unroll 1
    for (int kc = 0; kc < 32; ++kc) {
        cp_wait0();
        __syncthreads();
        if (kc + 1 < 32) issue(kc + 1, (kc + 1) & 1);
        const float* xb  = sX  + (kc & 1) * STAGE_F;
        const float* wcb = sWc + (kc & 1) * STAGE_F;
        const float* wgb = sWg + (kc & 1) * STAGE_F;
#pragma unroll
        for (int kk = 0; kk < 4; ++kk) {
            int ks = kk * 8;
            uint32_t a[4][4];
#pragma unroll
            for (int mt = 0; mt < 4; ++mt) {
                int r = wm + mt * 16 + g;
                a[mt][0] = __float_as_uint(xb[r * TSTR + ks + t]);
                a[mt][1] = __float_as_uint(xb[(r + 8) * TSTR + ks + t]);
                a[mt][2] = __float_as_uint(xb[r * TSTR + ks + t + 4]);
                a[mt][3] = __float_as_uint(xb[(r + 8) * TSTR + ks + t + 4]);
            }
            uint32_t bC[4][2], bG[4][2];
#pragma unroll
            for (int nt = 0; nt < 4; ++nt) {
                int cn = wn + nt * 8 + g;
                bC[nt][0] = __float_as_uint(wcb[cn * TSTR + ks + t]);
                bC[nt][1] = __float_as_uint(wcb[cn * TSTR + ks + t + 4]);
                if (DUAL) {
                    bG[nt][0] = __float_as_uint(wgb[cn * TSTR + ks + t]);
                    bG[nt][1] = __float_as_uint(wgb[cn * TSTR + ks + t + 4]);
                }
            }
#pragma unroll
            for (int mt = 0; mt < 4; ++mt)
#pragma unroll
                for (int nt = 0; nt < 4; ++nt) {
                    mma8(accC[mt][nt], a[mt], bC[nt]);
                    if (DUAL) mma8(accG[mt][nt], a[mt], bG[nt]);
                }
        }
    }
}

__global__ __launch_bounds__(256, 1) void fused_ssm_tc(
    const float* __restrict__ bc, const float* __restrict__ bcg,
    const float* __restrict__ bd, const float* __restrict__ bv)
{
    extern __shared__ float sm[];
    float* sX  = sm;                       // [2][128][36]
    float* sWc = sm + 2 * STAGE_F;         // [2][128][36]
    float* sWg = sm + 4 * STAGE_F;         // [2][128][36]
    float* sS  = sm + 6 * STAGE_F;         // [128][136]
    float* sHS = sS + 128 * 136;           // [128][17]

    const int tid = threadIdx.x;
    const int wid = tid >> 5, lane = tid & 31;
    const int g = lane >> 2, t = lane & 3;
    const int wm = (wid >> 2) * 64;
    const int wn = (wid & 3) * 32;
    const int mBase = blockIdx.y * 128;
    const int nBase = blockIdx.x * 128;

    for (int i = tid; i < 128 * 136; i += 256) sS[i] = 0.f;
    for (int i = tid; i < 128 * 16; i += 256) {
        int r = i >> 4, h = i & 15;
        sHS[r * 17 + h] = g_hs[(size_t)(mBase + r) * HH + h];
    }
    __syncthreads();

    uint32_t sXu  = (uint32_t)__cvta_generic_to_shared(sX);
    uint32_t sWcu = (uint32_t)__cvta_generic_to_shared(sWc);
    uint32_t sWgu = (uint32_t)__cvta_generic_to_shared(sWg);

    float accC[4][4][4], accG[4][4][4];

    for (int pass = 0; pass < HH; ++pass) {
#pragma unroll
        for (int mt = 0; mt < 4; ++mt)
#pragma unroll
            for (int nt = 0; nt < 4; ++nt)
#pragma unroll
                for (int k = 0; k < 4; ++k) { accC[mt][nt][k] = 0.f; accG[mt][nt][k] = 0.f; }

        gemm_pass<true>(g_Wc_t + (size_t)pass * OO * DD,
                        g_Wcg_t + (size_t)pass * OO * DD,
                        sX, sWc, sWg, sXu, sWcu, sWgu,
                        tid, g, t, wm, wn, mBase, nBase, accC, accG);

        // epilogue: gate, scale by hs, accumulate into sS
#pragma unroll
        for (int mt = 0; mt < 4; ++mt) {
            int r0 = wm + mt * 16 + g;
            float hs0 = sHS[r0 * 17 + pass];
            float hs1 = sHS[(r0 + 8) * 17 + pass];
#pragma unroll
            for (int nt = 0; nt < 4; ++nt) {
                int c0 = wn + nt * 8 + 2 * t;
                int cg0 = nBase + c0;
                float bc0 = __ldg(&bc[pass * OO + cg0]);
                float bc1 = __ldg(&bc[pass * OO + cg0 + 1]);
                float bg0 = __ldg(&bcg[pass * OO + cg0]);
                float bg1 = __ldg(&bcg[pass * OO + cg0 + 1]);
                float* s0 = &sS[r0 * 136 + c0];
                float* s1 = &sS[(r0 + 8) * 136 + c0];
                s0[0] += hs0 * (accC[mt][nt][0] + bc0) * sigm(accG[mt][nt][0] + bg0);
                s0[1] += hs0 * (accC[mt][nt][1] + bc1) * sigm(accG[mt][nt][1] + bg1);
                s1[0] += hs1 * (accC[mt][nt][2] + bc0) * sigm(accG[mt][nt][2] + bg0);
                s1[1] += hs1 * (accC[mt][nt][3] + bc1) * sigm(accG[mt][nt][3] + bg1);
            }
        }
    }

    // Wd pass (single matrix)
#pragma unroll
    for (int mt = 0; mt < 4; ++mt)
#pragma unroll
        for (int nt = 0; nt < 4; ++nt)
#pragma unroll
            for (int k = 0; k < 4; ++k) accC[mt][nt][k] = 0.f;

    gemm_pass<false>(g_Wd_t, g_Wd_t, sX, sWc, sWg, sXu, sWcu, sWgu,
                     tid, g, t, wm, wn, mBase, nBase, accC, accG);

#pragma unroll
    for (int mt = 0; mt < 4; ++mt) {
        int r0 = wm + mt * 16 + g;
#pragma unroll
        for (int nt = 0; nt < 4; ++nt) {
            int c0 = wn + nt * 8 + 2 * t;
            int cg0 = nBase + c0;
            float bd0 = __ldg(&bd[cg0]);
            float bd1 = __ldg(&bd[cg0 + 1]);
            float* s0 = &sS[r0 * 136 + c0];
            float* s1 = &sS[(r0 + 8) * 136 + c0];
            s0[0] += accC[mt][nt][0] + bd0;
            s0[1] += accC[mt][nt][1] + bd1;
            s1[0] += accC[mt][nt][2] + bd0;
            s1[1] += accC[mt][nt][3] + bd1;
        }
    }

    // y = batch_vectors + ssm
#pragma unroll
    for (int mt = 0; mt < 4; ++mt) {
        int r0 = wm + mt * 16 + g;
#pragma unroll
        for (int nt = 0; nt < 4; ++nt) {
            int c0 = wn + nt * 8 + 2 * t;
#pragma unroll
            for (int half = 0; half < 2; ++half) {
                int r = r0 + 8 * half;
                size_t gaddr = (size_t)(mBase + r) * DD + nBase + c0;
                float2 bvv = *reinterpret_cast<const float2*>(&bv[gaddr]);
                float2 sv  = *reinterpret_cast<float2*>(&sS[r * 136 + c0]);
                float2 o; o.x = bvv.x + sv.x; o.y = bvv.y + sv.y;
                *reinterpret_cast<float2*>(&g_y[gaddr]) = o;
            }
        }
    }
}

// ============================================================================
// FFN GEMM1 + exact GeLU (tf32): g_t = round(gelu(g_x3t @ W1_t.T + b1))
// ============================================================================
__global__ __launch_bounds__(256) void ffn1_tc(const float* __restrict__ b1) {
    extern __shared__ float sm[];
    float* sX = sm;
    float* sW = sm + 2 * STAGE_F;
    const int tid = threadIdx.x;
    const int wid = tid >> 5, lane = tid & 31;
    const int g = lane >> 2, t = lane & 3;
    const int wm = (wid >> 2) * 64;
    const int wn = (wid & 3) * 32;
    const int mBase = blockIdx.y * 128;
    const int nBase = blockIdx.x * 128;
    uint32_t sXu = (uint32_t)__cvta_generic_to_shared(sX);
    uint32_t sWu = (uint32_t)__cvta_generic_to_shared(sW);

    float acc[4][4][4];
#pragma unroll
    for (int mt = 0; mt < 4; ++mt)
#pragma unroll
        for (int nt = 0; nt < 4; ++nt)
#pragma unroll
            for (int k = 0; k < 4; ++k) acc[mt][nt][k] = 0.f;

    auto issue = [&](int kc, int st) {
        int k0 = kc * 32;
#pragma unroll
        for (int i = 0; i < 4; i++) {
            int j = tid + i * 256; int row = j >> 3; int c = (j & 7) * 4;
            cp16(sXu + (uint32_t)(((st * 128 + row) * TSTR) + c) * 4,
                 &g_x3t[(size_t)(mBase + row) * DD + k0 + c]);
        }
#pragma unroll
        for (int i = 0; i < 4; i++) {
            int j = tid + i * 256; int row = j >> 3; int c = (j & 7) * 4;
            cp16(sWu + (uint32_t)(((st * 128 + row) * TSTR) + c) * 4,
                 &g_W1_t[(size_t)(nBase + row) * DD + k0 + c]);
        }
        cp_commit();
    };

    issue(0, 0);
#pragma unroll 1
    for (int kc = 0; kc < 32; ++kc) {
        cp_wait0();
        __syncthreads();
        if (kc + 1 < 32) issue(kc + 1, (kc + 1) & 1);
        const float* xb = sX + (kc & 1) * STAGE_F;
        const float* wb = sW + (kc & 1) * STAGE_F;
#pragma unroll
        for (int kk = 0; kk < 4; ++kk) {
            int ks = kk * 8;
            uint32_t a[4][4], b[4][2];
#pragma unroll
            for (int mt = 0; mt < 4; ++mt) {
                int r = wm + mt * 16 + g;
                a[mt][0] = __float_as_uint(xb[r * TSTR + ks + t]);
                a[mt][1] = __float_as_uint(xb[(r + 8) * TSTR + ks + t]);
                a[mt][2] = __float_as_uint(xb[r * TSTR + ks + t + 4]);
                a[mt][3] = __float_as_uint(xb[(r + 8) * TSTR + ks + t + 4]);
            }
#pragma unroll
            for (int nt = 0; nt < 4; ++nt) {
                int cn = wn + nt * 8 + g;
                b[nt][0] = __float_as_uint(wb[cn * TSTR + ks + t]);
                b[nt][1] = __float_as_uint(wb[cn * TSTR + ks + t + 4]);
            }
#pragma unroll
            for (int mt = 0; mt < 4; ++mt)
#pragma unroll
                for (int nt = 0; nt < 4; ++nt) mma8(acc[mt][nt], a[mt], b[nt]);
        }
    }

#pragma unroll
    for (int mt = 0; mt < 4; ++mt) {
        int r0 = wm + mt * 16 + g;
#pragma unroll
        for (int nt = 0; nt < 4; ++nt) {
            int c0 = wn + nt * 8 + 2 * t;
            int nc = nBase + c0;
            float bb0 = __ldg(&b1[nc]), bb1 = __ldg(&b1[nc + 1]);
#pragma unroll
            for (int half = 0; half < 2; ++half) {
                int r = r0 + 8 * half;
                float v0 = acc[mt][nt][half * 2 + 0] + bb0;
                float v1 = acc[mt][nt][half * 2 + 1] + bb1;
                v0 = 0.5f * v0 * (1.0f + erff(v0 * 0.70710678118654752f));
                v1 = 0.5f * v1 * (1.0f + erff(v1 * 0.70710678118654752f));
                float2 o; o.x = tf32r(v0); o.y = tf32r(v1);
                *reinterpret_cast<float2*>(&g_t[(size_t)(mBase + r) * FF + nc]) = o;
            }
        }
    }
}

// ============================================================================
// FFN GEMM2 + residual (tf32): out = g_x3 + g_t @ W2_t.T + b2   (K=4096)
// ============================================================================
__global__ __launch_bounds__(256) void ffn2_tc(const float* __restrict__ b2,
                                               float* __restrict__ out) {
    extern __shared__ float sm[];
    float* sX = sm;
    float* sW = sm + 2 * STAGE_F;
    const int tid = threadIdx.x;
    const int wid = tid >> 5, lane = tid & 31;
    const int g = lane >> 2, t = lane & 3;
    const int wm = (wid >> 2) * 64;
    const int wn = (wid & 3) * 32;
    const int mBase = blockIdx.y * 128;
    const int nBase = blockIdx.x * 128;
    uint32_t sXu = (uint32_t)__cvta_generic_to_shared(sX);
    uint32_t sWu = (uint32_t)__cvta_generic_to_shared(sW);

    float acc[4][4][4];
#pragma unroll
    for (int mt = 0; mt < 4; ++mt)
#pragma unroll
        for (int nt = 0; nt < 4; ++nt)
#pragma unroll
            for (int k = 0; k < 4; ++k) acc[mt][nt][k] = 0.f;

    auto issue = [&](int kc, int st) {
        int k0 = kc * 32;
#pragma unroll
        for (int i = 0; i < 4; i++) {
            int j = tid + i * 256; int row = j >> 3; int c = (j & 7) * 4;
            cp16(sXu + (uint32_t)(((st * 128 + row) * TSTR) + c) * 4,
                 &g_t[(size_t)(mBase + row) * FF + k0 + c]);
        }
#pragma unroll
        for (int i = 0; i < 4; i++) {
            int j = tid + i * 256; int row = j >> 3; int c = (j & 7) * 4;
            cp16(sWu + (uint32_t)(((st * 128 + row) * TSTR) + c) * 4,
                 &g_W2_t[(size_t)(nBase + row) * FF + k0 + c]);
        }
        cp_commit();
    };

    issue(0, 0);
#pragma unroll 1
    for (int kc = 0; kc < 128; ++kc) {
        cp_wait0();
        __syncthreads();
        if (kc + 1 < 128) issue(kc + 1, (kc + 1) & 1);
        const float* xb = sX + (kc & 1) * STAGE_F;
        const float* wb = sW + (kc & 1) * STAGE_F;
#pragma unroll
        for (int kk = 0; kk < 4; ++kk) {
            int ks = kk * 8;
            uint32_t a[4][4], b[4][2];
#pragma unroll
            for (int mt = 0; mt < 4; ++mt) {
                int r = wm + mt * 16 + g;
                a[mt][0] = __float_as_uint(xb[r * TSTR + ks + t]);
                a[mt][1] = __float_as_uint(xb[(r + 8) * TSTR + ks + t]);
                a[mt][2] = __float_as_uint(xb[r * TSTR + ks + t + 4]);
                a[mt][3] = __float_as_uint(xb[(r + 8) * TSTR + ks + t + 4]);
            }
#pragma unroll
            for (int nt = 0; nt < 4; ++nt) {
                int cn = wn + nt * 8 + g;
                b[nt][0] = __float_as_uint(wb[cn * TSTR + ks + t]);
                b[nt][1] = __float_as_uint(wb[cn * TSTR + ks + t + 4]);
            }
#pragma unroll
            for (int mt = 0; mt < 4; ++mt)
#pragma unroll
                for (int nt = 0; nt < 4; ++nt) mma8(acc[mt][nt], a[mt], b[nt]);
        }
    }

#pragma unroll
    for (int mt = 0; mt < 4; ++mt) {
        int r0 = wm + mt * 16 + g;
#pragma unroll
        for (int nt = 0; nt < 4; ++nt) {
            int c0 = wn + nt * 8 + 2 * t;
            int nc = nBase + c0;
            float bb0 = __ldg(&b2[nc]), bb1 = __ldg(&b2[nc + 1]);
#pragma unroll
            for (int half = 0; half < 2; ++half) {
                int r = r0 + 8 * half;
                size_t gaddr = (size_t)(mBase + r) * DD + nc;
                float2 x3v = *reinterpret_cast<const float2*>(&g_x3[gaddr]);
                float2 o;
                o.x = x3v.x + acc[mt][nt][half * 2 + 0] + bb0;
                o.y = x3v.y + acc[mt][nt][half * 2 + 1] + bb1;
                *reinterpret_cast<float2*>(&out[gaddr]) = o;
            }
        }
    }
}

// ---------------------------------------------------------------------------
extern "C" void kernel_launch(void* const* d_in, const int* in_sizes, int n_in,
                              void* d_out, int out_size) {
    const float* bv  = (const float*)d_in[0];
    const float* h0  = (const float*)d_in[1];
    const float* A   = (const float*)d_in[2];
    const float* Wb  = (const float*)d_in[3];
    const float* bb  = (const float*)d_in[4];
    const float* Wc  = (const float*)d_in[5];
    const float* bc  = (const float*)d_in[6];
    const float* Wd  = (const float*)d_in[7];
    const float* bd  = (const float*)d_in[8];
    const float* Wbg = (const float*)d_in[9];
    const float* bbg = (const float*)d_in[10];
    const float* Wcg = (const float*)d_in[11];
    const float* bcg = (const float*)d_in[12];
    const float* W1  = (const float*)d_in[13];
    const float* b1  = (const float*)d_in[14];
    const float* W2  = (const float*)d_in[15];
    const float* b2  = (const float*)d_in[16];
    const float* g1  = (const float*)d_in[17];
    const float* be1 = (const float*)d_in[18];
    const float* g2  = (const float*)d_in[19];
    const float* be2 = (const float*)d_in[20];

    float* out = (float*)d_out;
    const int X_ELEMS = BL * DD;
    int write_last = (out_size >= X_ELEMS + BSZN * HH) ? 1 : 0;
    float* lasth = out + X_ELEMS;

    const int FUSED_SMEM = (6 * STAGE_F + 128 * 136 + 128 * 17) * 4;  // 188928
    const int FFN_SMEM   = (4 * STAGE_F) * 4;                          // 73728
    cudaFuncSetAttribute(fused_ssm_tc, cudaFuncAttributeMaxDynamicSharedMemorySize, FUSED_SMEM);
    cudaFuncSetAttribute(ffn1_tc, cudaFuncAttributeMaxDynamicSharedMemorySize, FFN_SMEM);
    cudaFuncSetAttribute(ffn2_tc, cudaFuncAttributeMaxDynamicSharedMemorySize, FFN_SMEM);

    // tf32-round all GEMM weights into scratch
    cvt_kernel<<<(HH * OO * DD / 4 + 255) / 256, 256>>>(Wc,  0, HH * OO * DD / 4);
    cvt_kernel<<<(HH * OO * DD / 4 + 255) / 256, 256>>>(Wcg, 1, HH * OO * DD / 4);
    cvt_kernel<<<(OO * DD / 4 + 255) / 256, 256>>>(Wd, 2, OO * DD / 4);
    cvt_kernel<<<(FF * DD / 4 + 255) / 256, 256>>>(W1, 3, FF * DD / 4);
    cvt_kernel<<<(DD * FF / 4 + 255) / 256, 256>>>(W2, 4, DD * FF / 4);

    ln_kernel<<<BL, 256>>>(bv, g1, be1, 0);
    projB_kernel<<<BL, 256>>>(Wb, bb, Wbg, bbg);
    scan_kernel<<<1, 64>>>(h0, A, lasth, write_last);

    {
        dim3 grid(OO / 128, BL / 128);   // (8, 32)
        fused_ssm_tc<<<grid, 256, FUSED_SMEM>>>(bc, bcg, bd, bv);
    }
    ln_kernel<<<BL, 256>>>(bv, g2, be2, 1);
    {
        dim3 grid(FF / 128, BL / 128);   // (32, 32)
        ffn1_tc<<<grid, 256, FFN_SMEM>>>(b1);
    }
    {
        dim3 grid(DD / 128, BL / 128);   // (8, 32)
        ffn2_tc<<<grid, 256, FFN_SMEM>>>(b2, out);
    }
}

// round 4
// speedup vs baseline: 8.6098x; 2.3031x over previous
#include <cuda_runtime.h>
#include <math.h>
#include <stdint.h>

#define BL   4096
#define DD   1024
#define HH   16
#define OO   1024
#define FF   4096
#define LSEQ 1024
#define BSZN 4

// Arch-specific (sm_103a) feature gate: tcgen05 only compiles in the 'a' pass.
#if defined(__CUDA_ARCH__)
#  if defined(__CUDA_ARCH_FEAT_SM103_ALL) || defined(__CUDA_ARCH_FEAT_SM100_ALL) || \
      (defined(__CUDA_ARCH_SPECIFIC__) && (__CUDA_ARCH_SPECIFIC__ >= 1000))
#    define T5_OK 1
#  else
#    define T5_OK 0
#  endif
#else
#  define T5_OK 0
#endif

// ---------------- scratch (device globals; no allocation allowed) ----------
__device__ float g_xln [BL * DD];
__device__ float g_xlnt[BL * DD];
__device__ float g_Bg  [BL * HH];
__device__ float g_hs  [BL * HH];
__device__ float g_y   [BL * DD];
__device__ float g_x3  [BL * DD];
__device__ float g_x3t [BL * DD];
__device__ float g_t   [BL * FF];
__device__ float g_Wc_t [HH * OO * DD];
__device__ float g_Wcg_t[HH * OO * DD];
__device__ float g_Wd_t [OO * DD];
__device__ float g_W1_t [FF * DD];
__device__ float g_W2_t [DD * FF];

// ---------------- basic helpers --------------------------------------------
__device__ __forceinline__ float tf32r(float f) {
    uint32_t u;
    asm("cvt.rna.tf32.f32 %0, %1;" : "=r"(u) : "f"(f));
    return __uint_as_float(u);
}
__device__ __forceinline__ float sigm(float x) { return 1.f / (1.f + __expf(-x)); }

__device__ __forceinline__ void cp16(uint32_t s, const float* gp) {
    asm volatile("cp.async.cg.shared.global [%0], [%1], 16;" :: "r"(s), "l"(gp));
}
__device__ __forceinline__ void cp_commit() { asm volatile("cp.async.commit_group;"); }
template <int N>
__device__ __forceinline__ void cp_wait() { asm volatile("cp.async.wait_group %0;" :: "n"(N)); }

// legacy mma.sync (fallback path, works on all sm_80+)
__device__ __forceinline__ void mma8(float* c, const uint32_t* a, const uint32_t* b) {
    asm volatile(
        "mma.sync.aligned.m16n8k8.row.col.f32.tf32.tf32.f32 "
        "{%0,%1,%2,%3},{%4,%5,%6,%7},{%8,%9},{%0,%1,%2,%3};"
        : "+f"(c[0]), "+f"(c[1]), "+f"(c[2]), "+f"(c[3])
        : "r"(a[0]), "r"(a[1]), "r"(a[2]), "r"(a[3]), "r"(b[0]), "r"(b[1]));
}

__device__ __forceinline__ bool elect1() {
    uint32_t p;
    asm volatile("{\n\t.reg .pred p;\n\telect.sync _|p, 0xFFFFFFFF;\n\tselp.b32 %0,1,0,p;\n\t}"
                 : "=r"(p));
    return p != 0;
}
__device__ __forceinline__ void mbar_init(uint32_t a, uint32_t cnt) {
    asm volatile("mbarrier.init.shared.b64 [%0], %1;" :: "r"(a), "r"(cnt) : "memory");
}
__device__ __forceinline__ void mbar_wait(uint32_t a, uint32_t parity) {
    asm volatile(
        "{\n\t.reg .pred P;\n"
        "WL%=:\n\t"
        "mbarrier.try_wait.parity.acquire.cta.shared::cta.b64 P, [%0], %1, 0x989680;\n\t"
        "@P bra WD%=;\n\t"
        "bra.uni WL%=;\n"
        "WD%=:\n\t}"
        :: "r"(a), "r"(parity) : "memory");
}

// ---------------- tcgen05 helpers (only instantiated under T5_OK) ----------
__device__ __forceinline__ void t5_alloc(uint32_t slot, uint32_t ncols) {
    asm volatile("tcgen05.alloc.cta_group::1.sync.aligned.shared::cta.b32 [%0], %1;"
                 :: "r"(slot), "r"(ncols) : "memory");
}
__device__ __forceinline__ void t5_relinquish() {
    asm volatile("tcgen05.relinquish_alloc_permit.cta_group::1.sync.aligned;");
}
__device__ __forceinline__ void t5_dealloc(uint32_t base, uint32_t ncols) {
    asm volatile("tcgen05.dealloc.cta_group::1.sync.aligned.b32 %0, %1;"
                 :: "r"(base), "r"(ncols));
}
__device__ __forceinline__ void t5_commit(uint32_t mbar) {
    asm volatile("tcgen05.commit.cta_group::1.mbarrier::arrive::one.shared::cluster.b64 [%0];"
                 :: "r"(mbar) : "memory");
}
__device__ __forceinline__ void t5_wait_ld() {
    asm volatile("tcgen05.wait::ld.sync.aligned;" ::: "memory");
}
__device__ __forceinline__ void t5_fence_after() {
    asm volatile("tcgen05.fence::after_thread_sync;" ::: "memory");
}
__device__ __forceinline__ void t5_fence_before() {
    asm volatile("tcgen05.fence::before_thread_sync;" ::: "memory");
}
__device__ __forceinline__ void fence_proxy_async_s() {
    asm volatile("fence.proxy.async.shared::cta;" ::: "memory");
}

// idesc for kind::tf32: c=F32(1@[4:5]), a=b=TF32(2@[7:9],[10:12]), N=128, M=128
#define IDESC_TF32 ((1u << 4) | (2u << 7) | (2u << 10) | ((128u / 8) << 17) | ((128u / 16) << 24))

__device__ __forceinline__ uint64_t mkdesc(uint32_t addr) {
    return ((uint64_t)2 << 61) | ((uint64_t)1 << 46) | ((uint64_t)64 << 32)
         | ((uint64_t)1 << 16) | ((addr >> 4) & 0x3FFF);
}
__device__ __forceinline__ void mma_tf32(uint32_t d, uint64_t a, uint64_t b, bool en) {
    uint32_t e = en ? 1u : 0u;
    asm volatile(
        "{\n\t.reg .pred p;\n\t"
        "setp.ne.u32 p, %4, 0;\n\t"
        "tcgen05.mma.cta_group::1.kind::tf32 [%0], %1, %2, %3, {%5, %5, %5, %5}, p;\n\t}"
        :: "r"(d), "l"(a), "l"(b), "r"(IDESC_TF32), "r"(e), "r"(0u) : "memory");
}
__device__ __forceinline__ void ldtm_x16(uint32_t* r, uint32_t a) {
    asm volatile(
        "tcgen05.ld.sync.aligned.32x32b.x16.b32 "
        "{%0,%1,%2,%3,%4,%5,%6,%7,%8,%9,%10,%11,%12,%13,%14,%15}, [%16];"
        : "=r"(r[0]),  "=r"(r[1]),  "=r"(r[2]),  "=r"(r[3]),
          "=r"(r[4]),  "=r"(r[5]),  "=r"(r[6]),  "=r"(r[7]),
          "=r"(r[8]),  "=r"(r[9]),  "=r"(r[10]), "=r"(r[11]),
          "=r"(r[12]), "=r"(r[13]), "=r"(r[14]), "=r"(r[15])
        : "r"(a));
}
__device__ __forceinline__ void ldtm_x32(uint32_t* r, uint32_t a) {
    asm volatile(
        "tcgen05.ld.sync.aligned.32x32b.x32.b32 "
        "{%0,%1,%2,%3,%4,%5,%6,%7,%8,%9,%10,%11,%12,%13,%14,%15,"
        "%16,%17,%18,%19,%20,%21,%22,%23,%24,%25,%26,%27,%28,%29,%30,%31}, [%32];"
        : "=r"(r[0]),  "=r"(r[1]),  "=r"(r[2]),  "=r"(r[3]),
          "=r"(r[4]),  "=r"(r[5]),  "=r"(r[6]),  "=r"(r[7]),
          "=r"(r[8]),  "=r"(r[9]),  "=r"(r[10]), "=r"(r[11]),
          "=r"(r[12]), "=r"(r[13]), "=r"(r[14]), "=r"(r[15]),
          "=r"(r[16]), "=r"(r[17]), "=r"(r[18]), "=r"(r[19]),
          "=r"(r[20]), "=r"(r[21]), "=r"(r[22]), "=r"(r[23]),
          "=r"(r[24]), "=r"(r[25]), "=r"(r[26]), "=r"(r[27]),
          "=r"(r[28]), "=r"(r[29]), "=r"(r[30]), "=r"(r[31])
        : "r"(a));
}

// ---------------- tf32 rounding conversion ---------------------------------
__global__ void cvt_kernel(const float* __restrict__ src, int which, int n4) {
    int i = blockIdx.x * blockDim.x + threadIdx.x;
    if (i >= n4) return;
    float4 v = ((const float4*)src)[i];
    v.x = tf32r(v.x); v.y = tf32r(v.y); v.z = tf32r(v.z); v.w = tf32r(v.w);
    float4* dst;
    switch (which) {
        case 0: dst = (float4*)g_Wc_t;  break;
        case 1: dst = (float4*)g_Wcg_t; break;
        case 2: dst = (float4*)g_Wd_t;  break;
        case 3: dst = (float4*)g_W1_t;  break;
        default: dst = (float4*)g_W2_t; break;
    }
    dst[i] = v;
}

// ---------------- LayerNorm --------------------------------------------------
__global__ void ln_kernel(const float* __restrict__ src,
                          const float* __restrict__ gw,
                          const float* __restrict__ bw, int mode) {
    int row = blockIdx.x;
    int tid = threadIdx.x;
    const float* x = (mode == 0 ? src : g_y) + (size_t)row * DD;
    float* dst  = (mode == 0 ? g_xln  : g_x3)  + (size_t)row * DD;
    float* dstt = (mode == 0 ? g_xlnt : g_x3t) + (size_t)row * DD;

    float v[4];
    float s = 0.f, s2 = 0.f;
#pragma unroll
    for (int i = 0; i < 4; i++) {
        v[i] = x[tid + 256 * i];
        s += v[i]; s2 += v[i] * v[i];
    }
#pragma unroll
    for (int o = 16; o > 0; o >>= 1) {
        s  += __shfl_down_sync(0xffffffffu, s,  o);
        s2 += __shfl_down_sync(0xffffffffu, s2, o);
    }
    __shared__ float rs[8], rs2[8], stats[2];
    int warp = tid >> 5, lane = tid & 31;
    if (lane == 0) { rs[warp] = s; rs2[warp] = s2; }
    __syncthreads();
    if (tid == 0) {
        float a = 0.f, b = 0.f;
#pragma unroll
        for (int i = 0; i < 8; i++) { a += rs[i]; b += rs2[i]; }
        float mean = a * (1.0f / DD);
        float var  = b * (1.0f / DD) - mean * mean;
        stats[0] = mean; stats[1] = rsqrtf(var + 1e-5f);
    }
    __syncthreads();
    float mean = stats[0], rstd = stats[1];
#pragma unroll
    for (int i = 0; i < 4; i++) {
        int c = tid + 256 * i;
        float o = (v[i] - mean) * rstd * gw[c] + bw[c];
        dst[c]  = o;
        dstt[c] = tf32r(o);
    }
}

// ---------------- B projection + gate ----------------------------------------
__global__ void projB_kernel(const float* __restrict__ Wb,
                             const float* __restrict__ bb,
                             const float* __restrict__ Wbg,
                             const float* __restrict__ bbg) {
    int row = blockIdx.x;
    int warp = threadIdx.x >> 5, lane = threadIdx.x & 31;
    const float* x = g_xln + (size_t)row * DD;
    for (int h = warp; h < HH; h += 8) {
        const float* wb = Wb  + (size_t)h * DD;
        const float* wg = Wbg + (size_t)h * DD;
        float sb = 0.f, sg = 0.f;
        for (int k = lane; k < DD; k += 32) {
            float xv = x[k];
            sb += xv * wb[k];
            sg += xv * wg[k];
        }
#pragma unroll
        for (int o = 16; o > 0; o >>= 1) {
            sb += __shfl_down_sync(0xffffffffu, sb, o);
            sg += __shfl_down_sync(0xffffffffu, sg, o);
        }
        if (lane == 0) {
            float bval = sb + bb[h];
            float gval = sg + bbg[h];
            g_Bg[(size_t)row * HH + h] = bval * (1.f / (1.f + expf(-gval)));
        }
    }
}

// ---------------- selective scan ----------------------------------------------
__global__ void scan_kernel(const float* __restrict__ h0,
                            const float* __restrict__ A,
                            float* __restrict__ lasth, int write_last) {
    int tt = threadIdx.x;
    if (tt >= BSZN * HH) return;
    int b = tt / HH, h = tt % HH;
    float dA = expf(A[h]);
    float hc = h0[b * HH + h];
    const float* bp = g_Bg + (size_t)b * LSEQ * HH + h;
    float* hp = g_hs + (size_t)b * LSEQ * HH + h;
#pragma unroll 4
    for (int l = 0; l < LSEQ; l++) {
        hc = dA * hc + bp[(size_t)l * HH];
        hp[(size_t)l * HH] = hc;
    }
    if (write_last) lasth[b * HH + h] = hc;
}

// ---------------- fallback mma.sync GEMM pass (R2-proven) -------------------
#define TSTR 36
#define STAGE_F (128 * TSTR)

template <bool DUAL>
__device__ __forceinline__ void fb_gemm_pass(
    const float* __restrict__ W0, const float* __restrict__ W1p,
    const float* sX, const float* sWc, const float* sWg,
    uint32_t sXu, uint32_t sWcu, uint32_t sWgu,
    int tid, int g, int t, int wm, int wn, int mBase, int nBase,
    float (*accC)[4][4], float (*accG)[4][4])
{
    auto issue = [&](int kc, int st) {
        int k0 = kc * 32;
#pragma unroll
        for (int i = 0; i < 4; i++) {
            int j = tid + i * 256; int row = j >> 3; int c = (j & 7) * 4;
            cp16(sXu + (uint32_t)(((st * 128 + row) * TSTR) + c) * 4,
                 &g_xlnt[(size_t)(mBase + row) * DD + k0 + c]);
        }
#pragma unroll
        for (int i = 0; i < 4; i++) {
            int j = tid + i * 256; int row = j >> 3; int c = (j & 7) * 4;
            cp16(sWcu + (uint32_t)(((st * 128 + row) * TSTR) + c) * 4,
                 &W0[(size_t)(nBase + row) * DD + k0 + c]);
        }
        if (DUAL) {
#pragma unroll
            for (int i = 0; i < 4; i++) {
                int j = tid + i * 256; int row = j >> 3; int c = (j & 7) * 4;
                cp16(sWgu + (uint32_t)(((st * 128 + row) * TSTR) + c) * 4,
                     &W1p[(size_t)(nBase + row) * DD + k0 + c]);
            }
        }
        cp_commit();
    };

    issue(0, 0);
#pragma unroll 1
    for (int kc = 0; kc < 32; ++kc) {
        cp_wait<0>();
        __syncthreads();
        if (kc + 1 < 32) issue(kc + 1, (kc + 1) & 1);
        const float* xb  = sX  + (kc & 1) * STAGE_F;
        const float* wcb = sWc + (kc & 1) * STAGE_F;
        const float* wgb = sWg + (kc & 1) * STAGE_F;
#pragma unroll
        for (int kk = 0; kk < 4; ++kk) {
            int ks = kk * 8;
            uint32_t a[4][4];
#pragma unroll
            for (int mt = 0; mt < 4; ++mt) {
                int r = wm + mt * 16 + g;
                a[mt][0] = __float_as_uint(xb[r * TSTR + ks + t]);
                a[mt][1] = __float_as_uint(xb[(r + 8) * TSTR + ks + t]);
                a[mt][2] = __float_as_uint(xb[r * TSTR + ks + t + 4]);
                a[mt][3] = __float_as_uint(xb[(r + 8) * TSTR + ks + t + 4]);
            }
            uint32_t bC[4][2], bG[4][2];
#pragma unroll
            for (int nt = 0; nt < 4; ++nt) {
                int cn = wn + nt * 8 + g;
                bC[nt][0] = __float_as_uint(wcb[cn * TSTR + ks + t]);
                bC[nt][1] = __float_as_uint(wcb[cn * TSTR + ks + t + 4]);
                if (DUAL) {
                    bG[nt][0] = __float_as_uint(wgb[cn * TSTR + ks + t]);
                    bG[nt][1] = __float_as_uint(wgb[cn * TSTR + ks + t + 4]);
                }
            }
#pragma unroll
            for (int mt = 0; mt < 4; ++mt)
#pragma unroll
                for (int nt = 0; nt < 4; ++nt) {
                    mma8(accC[mt][nt], a[mt], bC[nt]);
                    if (DUAL) mma8(accG[mt][nt], a[mt], bG[nt]);
                }
        }
        __syncthreads();
    }
}

// ============================================================================
// Fused SSM kernel. Grid: (OO/128, BL/256). One symbol, two arch bodies.
// ============================================================================
#define F_HS   2048
#define F_ST   19456
#define F_STSZ 65536
#define FUSED_SMEM (19456 + 3 * 65536 + 1024)

__global__ __launch_bounds__(256, 1)
void fused_ssm_t5(const float* __restrict__ bc, const float* __restrict__ bcg,
                  const float* __restrict__ bd, const float* __restrict__ bv)
{
    extern __shared__ char smraw[];
#if T5_OK
    // ---------------- tcgen05 path ----------------
    uint32_t sraw = (uint32_t)__cvta_generic_to_shared(smraw);
    uint32_t sbase = (sraw + 1023) & ~1023u;
    float* smf = (float*)(smraw + (sbase - sraw));
    float* sBC = smf + 32;
    float* sBG = smf + 160;
    float* sHS = smf + F_HS / 4;

    const int tid = threadIdx.x;
    const int wid = tid >> 5, lane = tid & 31;
    const int sp = wid & 3, ch = wid >> 2;
    const int mBase = blockIdx.y * 256;
    const int nBase = blockIdx.x * 128;

    if (wid == 0) t5_alloc(sbase, 512);
    if (tid == 0) {
        mbar_init(sbase + 8, 1);
        mbar_init(sbase + 16, 1);
        mbar_init(sbase + 24, 1);
    }
    for (int i = tid; i < 256 * 16; i += 256) {
        int r = i >> 4, h = i & 15;
        sHS[r * 17 + h] = g_hs[(size_t)(mBase + r) * HH + h];
    }
    __syncthreads();
    uint32_t tmem;
    asm volatile("ld.shared.b32 %0, [%1];" : "=r"(tmem) : "r"(sbase));
    if (wid == 0) t5_relinquish();

    float ssm[128];
#pragma unroll
    for (int i = 0; i < 128; i++) ssm[i] = 0.f;

    uint32_t wcnt[3] = {0, 0, 0};

    for (int head = 0; head < 17; ++head) {
        const bool dual = (head < 16);
        const float* Wc_h = dual ? (g_Wc_t  + (size_t)head * OO * DD) : g_Wd_t;
        const float* Wg_h = dual ? (g_Wcg_t + (size_t)head * OO * DD) : g_Wd_t;

        if (tid < 128) {
            sBC[tid] = dual ? bc[head * OO + nBase + tid] : bd[nBase + tid];
        } else if (dual) {
            sBG[tid - 128] = bcg[head * OO + nBase + (tid - 128)];
        }

        auto fill = [&](int kc, int st) {
            uint32_t sa = sbase + F_ST + st * F_STSZ;
            int k0 = kc * 32;
#pragma unroll
            for (int i = 0; i < 8; i++) {
                int id = tid + i * 256;
                int row = id >> 3, c = (id & 7) * 16;
                uint32_t off = (uint32_t)(row * 128 + c);
                uint32_t sw = off ^ ((off >> 3) & 0x70);
                cp16(sa + sw, &g_xlnt[(size_t)(mBase + row) * DD + k0 + (c >> 2)]);
            }
#pragma unroll
            for (int i = 0; i < 4; i++) {
                int id = tid + i * 256;
                int row = id >> 3, c = (id & 7) * 16;
                uint32_t off = (uint32_t)(row * 128 + c);
                uint32_t sw = off ^ ((off >> 3) & 0x70);
                cp16(sa + 32768 + sw, &Wc_h[(size_t)(nBase + row) * DD + k0 + (c >> 2)]);
                if (dual)
                    cp16(sa + 49152 + sw, &Wg_h[(size_t)(nBase + row) * DD + k0 + (c >> 2)]);
            }
            cp_commit();
        };

        fill(0, 0);
        fill(1, 1);
#pragma unroll 1
        for (int kc = 0; kc < 32; ++kc) {
            int s = kc % 3;
            if (kc < 31) cp_wait<1>(); else cp_wait<0>();
            fence_proxy_async_s();
            __syncthreads();
            if (wid == 0 && elect1()) {
                uint32_t sa = sbase + F_ST + s * F_STSZ;
                uint64_t dA0 = mkdesc(sa), dA1 = mkdesc(sa + 16384);
                uint64_t dBc = mkdesc(sa + 32768), dBg = mkdesc(sa + 49152);
#pragma unroll
                for (int ks = 0; ks < 4; ++ks) {
                    bool en = !(kc == 0 && ks == 0);
                    uint64_t o = (uint64_t)(ks * 2);
                    mma_tf32(tmem + 0,   dA0 + o, dBc + o, en);
                    mma_tf32(tmem + 128, dA1 + o, dBc + o, en);
                    if (dual) {
                        mma_tf32(tmem + 256, dA0 + o, dBg + o, en);
                        mma_tf32(tmem + 384, dA1 + o, dBg + o, en);
                    }
                }
                t5_commit(sbase + 8 + 8 * s);
            }
            if (kc + 2 < 32) {
                if (kc >= 1) {
                    int ps = (kc - 1) % 3;
                    mbar_wait(sbase + 8 + 8 * ps, wcnt[ps] & 1);
                    wcnt[ps]++;
                }
                fill(kc + 2, (kc + 2) % 3);
            }
        }
#pragma unroll
        for (int c = 29; c < 32; ++c) {
            int s = c % 3;
            mbar_wait(sbase + 8 + 8 * s, wcnt[s] & 1);
            wcnt[s]++;
        }

        __syncthreads();
        t5_fence_after();
#pragma unroll
        for (int s = 0; s < 2; ++s) {
            float hsv = 1.f;
            if (dual) hsv = sHS[(s * 128 + sp * 32 + lane) * 17 + head];
#pragma unroll
            for (int q = 0; q < 4; ++q) {
                uint32_t cb[16], gb[16];
                uint32_t ca = tmem + s * 128 + ch * 64 + q * 16;
                ldtm_x16(cb, ca);
                if (dual) ldtm_x16(gb, ca + 256);
                t5_wait_ld();
#pragma unroll
                for (int j = 0; j < 16; ++j) {
                    int col = ch * 64 + q * 16 + j;
                    float cc = __uint_as_float(cb[j]) + sBC[col];
                    if (dual) {
                        float gg = __uint_as_float(gb[j]) + sBG[col];
                        ssm[s * 64 + q * 16 + j] += hsv * cc * sigm(gg);
                    } else {
                        ssm[s * 64 + q * 16 + j] += cc;
                    }
                }
            }
        }
        t5_fence_before();
        __syncthreads();
    }

#pragma unroll
    for (int s = 0; s < 2; ++s) {
        int r = mBase + s * 128 + sp * 32 + lane;
        size_t ga = (size_t)r * DD + nBase + ch * 64;
#pragma unroll
        for (int q = 0; q < 16; ++q) {
            float4 b4 = *reinterpret_cast<const float4*>(&bv[ga + q * 4]);
            float4 o;
            o.x = b4.x + ssm[s * 64 + q * 4 + 0];
            o.y = b4.y + ssm[s * 64 + q * 4 + 1];
            o.z = b4.z + ssm[s * 64 + q * 4 + 2];
            o.w = b4.w + ssm[s * 64 + q * 4 + 3];
            *reinterpret_cast<float4*>(&g_y[ga + q * 4]) = o;
        }
    }

    __syncthreads();
    if (wid == 0) t5_dealloc(tmem, 512);
#else
    // ---------------- fallback: mma.sync (R2), 2 x M=128 subtiles ----------
    float* sm  = (float*)smraw;
    float* sX  = sm;
    float* sWc = sm + 2 * STAGE_F;
    float* sWg = sm + 4 * STAGE_F;
    float* sS  = sm + 6 * STAGE_F;          // [128][136]
    float* sHS = sS + 128 * 136;            // [128][17]

    const int tid = threadIdx.x;
    const int wid = tid >> 5, lane = tid & 31;
    const int g = lane >> 2, t = lane & 3;
    const int wm = (wid >> 2) * 64;
    const int wn = (wid & 3) * 32;
    const int nBase = blockIdx.x * 128;
    uint32_t sXu  = (uint32_t)__cvta_generic_to_shared(sX);
    uint32_t sWcu = (uint32_t)__cvta_generic_to_shared(sWc);
    uint32_t sWgu = (uint32_t)__cvta_generic_to_shared(sWg);

    for (int sub = 0; sub < 2; ++sub) {
        const int mBase = blockIdx.y * 256 + sub * 128;
        for (int i = tid; i < 128 * 136; i += 256) sS[i] = 0.f;
        for (int i = tid; i < 128 * 16; i += 256) {
            int r = i >> 4, h = i & 15;
            sHS[r * 17 + h] = g_hs[(size_t)(mBase + r) * HH + h];
        }
        __syncthreads();

        float accC[4][4][4], accG[4][4][4];
        for (int pass = 0; pass < HH; ++pass) {
#pragma unroll
            for (int mt = 0; mt < 4; ++mt)
#pragma unroll
                for (int nt = 0; nt < 4; ++nt)
#pragma unroll
                    for (int k = 0; k < 4; ++k) { accC[mt][nt][k] = 0.f; accG[mt][nt][k] = 0.f; }

            fb_gemm_pass<true>(g_Wc_t + (size_t)pass * OO * DD,
                               g_Wcg_t + (size_t)pass * OO * DD,
                               sX, sWc, sWg, sXu, sWcu, sWgu,
                               tid, g, t, wm, wn, mBase, nBase, accC, accG);

#pragma unroll
            for (int mt = 0; mt < 4; ++mt) {
                int r0 = wm + mt * 16 + g;
                float hs0 = sHS[r0 * 17 + pass];
                float hs1 = sHS[(r0 + 8) * 17 + pass];
#pragma unroll
                for (int nt = 0; nt < 4; ++nt) {
                    int c0 = wn + nt * 8 + 2 * t;
                    int cg0 = nBase + c0;
                    float bc0 = __ldg(&bc[pass * OO + cg0]);
                    float bc1 = __ldg(&bc[pass * OO + cg0 + 1]);
                    float bg0 = __ldg(&bcg[pass * OO + cg0]);
                    float bg1 = __ldg(&bcg[pass * OO + cg0 + 1]);
                    float* s0 = &sS[r0 * 136 + c0];
                    float* s1 = &sS[(r0 + 8) * 136 + c0];
                    s0[0] += hs0 * (accC[mt][nt][0] + bc0) * sigm(accG[mt][nt][0] + bg0);
                    s0[1] += hs0 * (accC[mt][nt][1] + bc1) * sigm(accG[mt][nt][1] + bg1);
                    s1[0] += hs1 * (accC[mt][nt][2] + bc0) * sigm(accG[mt][nt][2] + bg0);
                    s1[1] += hs1 * (accC[mt][nt][3] + bc1) * sigm(accG[mt][nt][3] + bg1);
                }
            }
        }

#pragma unroll
        for (int mt = 0; mt < 4; ++mt)
#pragma unroll
            for (int nt = 0; nt < 4; ++nt)
#pragma unroll
                for (int k = 0; k < 4; ++k) accC[mt][nt][k] = 0.f;

        fb_gemm_pass<false>(g_Wd_t, g_Wd_t, sX, sWc, sWg, sXu, sWcu, sWgu,
                            tid, g, t, wm, wn, mBase, nBase, accC, accG);

#pragma unroll
        for (int mt = 0; mt < 4; ++mt) {
            int r0 = wm + mt * 16 + g;
#pragma unroll
            for (int nt = 0; nt < 4; ++nt) {
                int c0 = wn + nt * 8 + 2 * t;
                int cg0 = nBase + c0;
                float bd0 = __ldg(&bd[cg0]);
                float bd1 = __ldg(&bd[cg0 + 1]);
                float* s0 = &sS[r0 * 136 + c0];
                float* s1 = &sS[(r0 + 8) * 136 + c0];
                s0[0] += accC[mt][nt][0] + bd0;
                s0[1] += accC[mt][nt][1] + bd1;
                s1[0] += accC[mt][nt][2] + bd0;
                s1[1] += accC[mt][nt][3] + bd1;
            }
        }

#pragma unroll
        for (int mt = 0; mt < 4; ++mt) {
            int r0 = wm + mt * 16 + g;
#pragma unroll
            for (int nt = 0; nt < 4; ++nt) {
                int c0 = wn + nt * 8 + 2 * t;
#pragma unroll
                for (int half = 0; half < 2; ++half) {
                    int r = r0 + 8 * half;
                    size_t gaddr = (size_t)(mBase + r) * DD + nBase + c0;
                    float2 bvv = *reinterpret_cast<const float2*>(&bv[gaddr]);
                    float2 sv  = *reinterpret_cast<float2*>(&sS[r * 136 + c0]);
                    float2 o; o.x = bvv.x + sv.x; o.y = bvv.y + sv.y;
                    *reinterpret_cast<float2*>(&g_y[gaddr]) = o;
                }
            }
        }
        __syncthreads();
    }
#endif
}

// ============================================================================
// Generic GEMM. Grid: (N/128, BL/256). One symbol, two arch bodies.
// MODE 0: outp = tf32r(gelu(A @ B.T + bias))      (stride out_stride)
// MODE 1: outp = res + A @ B.T + bias
// ============================================================================
#define G_ST   2048
#define G_STSZ 49152
#define GEMM_SMEM (2048 + 3 * 49152 + 1024)

template <int KDIM, int MODE>
__global__ __launch_bounds__(256, 1)
void gemm_t5(const float* __restrict__ Amat, const float* __restrict__ Bmat,
             const float* __restrict__ bias, const float* __restrict__ res,
             float* __restrict__ outp, int out_stride)
{
    extern __shared__ char smraw[];
#if T5_OK
    uint32_t sraw = (uint32_t)__cvta_generic_to_shared(smraw);
    uint32_t sbase = (sraw + 1023) & ~1023u;
    float* smf = (float*)(smraw + (sbase - sraw));
    float* sB = smf + 32;

    const int tid = threadIdx.x;
    const int wid = tid >> 5, lane = tid & 31;
    const int sp = wid & 3, ch = wid >> 2;
    const int mBase = blockIdx.y * 256;
    const int nBase = blockIdx.x * 128;
    const int NC = KDIM / 32;

    if (wid == 0) t5_alloc(sbase, 512);
    if (tid == 0) {
        mbar_init(sbase + 8, 1);
        mbar_init(sbase + 16, 1);
        mbar_init(sbase + 24, 1);
    }
    if (tid < 128) sB[tid] = bias[nBase + tid];
    __syncthreads();
    uint32_t tmem;
    asm volatile("ld.shared.b32 %0, [%1];" : "=r"(tmem) : "r"(sbase));
    if (wid == 0) t5_relinquish();

    uint32_t wcnt[3] = {0, 0, 0};

    auto fill = [&](int kc, int st) {
        uint32_t sa = sbase + G_ST + st * G_STSZ;
        int k0 = kc * 32;
#pragma unroll
        for (int i = 0; i < 8; i++) {
            int id = tid + i * 256;
            int row = id >> 3, c = (id & 7) * 16;
            uint32_t off = (uint32_t)(row * 128 + c);
            uint32_t sw = off ^ ((off >> 3) & 0x70);
            cp16(sa + sw, &Amat[(size_t)(mBase + row) * KDIM + k0 + (c >> 2)]);
        }
#pragma unroll
        for (int i = 0; i < 4; i++) {
            int id = tid + i * 256;
            int row = id >> 3, c = (id & 7) * 16;
            uint32_t off = (uint32_t)(row * 128 + c);
            uint32_t sw = off ^ ((off >> 3) & 0x70);
            cp16(sa + 32768 + sw, &Bmat[(size_t)(nBase + row) * KDIM + k0 + (c >> 2)]);
        }
        cp_commit();
    };

    fill(0, 0);
    fill(1, 1);
#pragma unroll 1
    for (int kc = 0; kc < NC; ++kc) {
        int s = kc % 3;
        if (kc < NC - 1) cp_wait<1>(); else cp_wait<0>();
        fence_proxy_async_s();
        __syncthreads();
        if (wid == 0 && elect1()) {
            uint32_t sa = sbase + G_ST + s * G_STSZ;
            uint64_t dA0 = mkdesc(sa), dA1 = mkdesc(sa + 16384);
            uint64_t dB = mkdesc(sa + 32768);
#pragma unroll
            for (int ks = 0; ks < 4; ++ks) {
                bool en = !(kc == 0 && ks == 0);
                uint64_t o = (uint64_t)(ks * 2);
                mma_tf32(tmem + 0,   dA0 + o, dB + o, en);
                mma_tf32(tmem + 128, dA1 + o, dB + o, en);
            }
            t5_commit(sbase + 8 + 8 * s);
        }
        if (kc + 2 < NC) {
            if (kc >= 1) {
                int ps = (kc - 1) % 3;
                mbar_wait(sbase + 8 + 8 * ps, wcnt[ps] & 1);
                wcnt[ps]++;
            }
            fill(kc + 2, (kc + 2) % 3);
        }
    }
#pragma unroll
    for (int c = NC - 3; c < NC; ++c) {
        int s = c % 3;
        mbar_wait(sbase + 8 + 8 * s, wcnt[s] & 1);
        wcnt[s]++;
    }

    __syncthreads();
    t5_fence_after();
#pragma unroll
    for (int s = 0; s < 2; ++s) {
        int r = mBase + s * 128 + sp * 32 + lane;
#pragma unroll
        for (int half = 0; half < 2; ++half) {
            uint32_t cb[32];
            ldtm_x32(cb, tmem + s * 128 + ch * 64 + half * 32);
            t5_wait_ld();
            float vout[32];
            size_t ga = (size_t)r * out_stride + nBase + ch * 64 + half * 32;
#pragma unroll
            for (int j = 0; j < 32; ++j) {
                int col = ch * 64 + half * 32 + j;
                float v = __uint_as_float(cb[j]) + sB[col];
                if (MODE == 0) {
                    v = 0.5f * v * (1.0f + erff(v * 0.70710678118654752f));
                    vout[j] = tf32r(v);
                } else {
                    vout[j] = v;
                }
            }
            if (MODE == 1) {
#pragma unroll
                for (int q = 0; q < 8; ++q) {
                    float4 r4 = *reinterpret_cast<const float4*>(&res[ga + q * 4]);
                    vout[q * 4 + 0] += r4.x;
                    vout[q * 4 + 1] += r4.y;
                    vout[q * 4 + 2] += r4.z;
                    vout[q * 4 + 3] += r4.w;
                }
            }
#pragma unroll
            for (int q = 0; q < 8; ++q) {
                float4 o;
                o.x = vout[q * 4 + 0]; o.y = vout[q * 4 + 1];
                o.z = vout[q * 4 + 2]; o.w = vout[q * 4 + 3];
                *reinterpret_cast<float4*>(&outp[ga + q * 4]) = o;
            }
        }
    }
    t5_fence_before();
    __syncthreads();
    if (wid == 0) t5_dealloc(tmem, 512);
#else
    // ---------------- fallback: mma.sync (R2 ffn), 2 x M=128 subtiles ------
    float* sm = (float*)smraw;
    float* sX = sm;
    float* sW = sm + 2 * STAGE_F;
    const int tid = threadIdx.x;
    const int wid = tid >> 5, lane = tid & 31;
    const int g = lane >> 2, t = lane & 3;
    const int wm = (wid >> 2) * 64;
    const int wn = (wid & 3) * 32;
    const int nBase = blockIdx.x * 128;
    uint32_t sXu = (uint32_t)__cvta_generic_to_shared(sX);
    uint32_t sWu = (uint32_t)__cvta_generic_to_shared(sW);
    const int NC = KDIM / 32;

    for (int sub = 0; sub < 2; ++sub) {
        const int mBase = blockIdx.y * 256 + sub * 128;
        float acc[4][4][4];
#pragma unroll
        for (int mt = 0; mt < 4; ++mt)
#pragma unroll
            for (int nt = 0; nt < 4; ++nt)
#pragma unroll
                for (int k = 0; k < 4; ++k) acc[mt][nt][k] = 0.f;

        auto issue = [&](int kc, int st) {
            int k0 = kc * 32;
#pragma unroll
            for (int i = 0; i < 4; i++) {
                int j = tid + i * 256; int row = j >> 3; int c = (j & 7) * 4;
                cp16(sXu + (uint32_t)(((st * 128 + row) * TSTR) + c) * 4,
                     &Amat[(size_t)(mBase + row) * KDIM + k0 + c]);
            }
#pragma unroll
            for (int i = 0; i < 4; i++) {
                int j = tid + i * 256; int row = j >> 3; int c = (j & 7) * 4;
                cp16(sWu + (uint32_t)(((st * 128 + row) * TSTR) + c) * 4,
                     &Bmat[(size_t)(nBase + row) * KDIM + k0 + c]);
            }
            cp_commit();
        };

        issue(0, 0);
#pragma unroll 1
        for (int kc = 0; kc < NC; ++kc) {
            cp_wait<0>();
            __syncthreads();
            if (kc + 1 < NC) issue(kc + 1, (kc + 1) & 1);
            const float* xb = sX + (kc & 1) * STAGE_F;
            const float* wb = sW + (kc & 1) * STAGE_F;
#pragma unroll
            for (int kk = 0; kk < 4; ++kk) {
                int ks = kk * 8;
                uint32_t a[4][4], b[4][2];
#pragma unroll
                for (int mt = 0; mt < 4; ++mt) {
                    int r = wm + mt * 16 + g;
                    a[mt][0] = __float_as_uint(xb[r * TSTR + ks + t]);
                    a[mt][1] = __float_as_uint(xb[(r + 8) * TSTR + ks + t]);
                    a[mt][2] = __float_as_uint(xb[r * TSTR + ks + t + 4]);
                    a[mt][3] = __float_as_uint(xb[(r + 8) * TSTR + ks + t + 4]);
                }
#pragma unroll
                for (int nt = 0; nt < 4; ++nt) {
                    int cn = wn + nt * 8 + g;
                    b[nt][0] = __float_as_uint(wb[cn * TSTR + ks + t]);
                    b[nt][1] = __float_as_uint(wb[cn * TSTR + ks + t + 4]);
                }
#pragma unroll
                for (int mt = 0; mt < 4; ++mt)
#pragma unroll
                    for (int nt = 0; nt < 4; ++nt) mma8(acc[mt][nt], a[mt], b[nt]);
            }
            __syncthreads();
        }

#pragma unroll
        for (int mt = 0; mt < 4; ++mt) {
            int r0 = wm + mt * 16 + g;
#pragma unroll
            for (int nt = 0; nt < 4; ++nt) {
                int c0 = wn + nt * 8 + 2 * t;
                int nc = nBase + c0;
                float bb0 = __ldg(&bias[nc]), bb1 = __ldg(&bias[nc + 1]);
#pragma unroll
                for (int half = 0; half < 2; ++half) {
                    int r = r0 + 8 * half;
                    size_t ga = (size_t)(mBase + r) * out_stride + nc;
                    float v0 = acc[mt][nt][half * 2 + 0] + bb0;
                    float v1 = acc[mt][nt][half * 2 + 1] + bb1;
                    float2 o;
                    if (MODE == 0) {
                        v0 = 0.5f * v0 * (1.0f + erff(v0 * 0.70710678118654752f));
                        v1 = 0.5f * v1 * (1.0f + erff(v1 * 0.70710678118654752f));
                        o.x = tf32r(v0); o.y = tf32r(v1);
                    } else {
                        float2 r4 = *reinterpret_cast<const float2*>(&res[ga]);
                        o.x = v0 + r4.x; o.y = v1 + r4.y;
                    }
                    *reinterpret_cast<float2*>(&outp[ga]) = o;
                }
            }
        }
        __syncthreads();
    }
#endif
}

// ---------------------------------------------------------------------------
extern "C" void kernel_launch(void* const* d_in, const int* in_sizes, int n_in,
                              void* d_out, int out_size) {
    const float* bv  = (const float*)d_in[0];
    const float* h0  = (const float*)d_in[1];
    const float* A   = (const float*)d_in[2];
    const float* Wb  = (const float*)d_in[3];
    const float* bb  = (const float*)d_in[4];
    const float* Wc  = (const float*)d_in[5];
    const float* bc  = (const float*)d_in[6];
    const float* Wd  = (const float*)d_in[7];
    const float* bd  = (const float*)d_in[8];
    const float* Wbg = (const float*)d_in[9];
    const float* bbg = (const float*)d_in[10];
    const float* Wcg = (const float*)d_in[11];
    const float* bcg = (const float*)d_in[12];
    const float* W1  = (const float*)d_in[13];
    const float* b1  = (const float*)d_in[14];
    const float* W2  = (const float*)d_in[15];
    const float* b2  = (const float*)d_in[16];
    const float* g1  = (const float*)d_in[17];
    const float* be1 = (const float*)d_in[18];
    const float* g2  = (const float*)d_in[19];
    const float* be2 = (const float*)d_in[20];

    float* out = (float*)d_out;
    const int X_ELEMS = BL * DD;
    int write_last = (out_size >= X_ELEMS + BSZN * HH) ? 1 : 0;
    float* lasth = out + X_ELEMS;

    cudaFuncSetAttribute(fused_ssm_t5, cudaFuncAttributeMaxDynamicSharedMemorySize, FUSED_SMEM);
    cudaFuncSetAttribute(gemm_t5<1024, 0>, cudaFuncAttributeMaxDynamicSharedMemorySize, GEMM_SMEM);
    cudaFuncSetAttribute(gemm_t5<4096, 1>, cudaFuncAttributeMaxDynamicSharedMemorySize, GEMM_SMEM);

    cvt_kernel<<<(HH * OO * DD / 4 + 255) / 256, 256>>>(Wc,  0, HH * OO * DD / 4);
    cvt_kernel<<<(HH * OO * DD / 4 + 255) / 256, 256>>>(Wcg, 1, HH * OO * DD / 4);
    cvt_kernel<<<(OO * DD / 4 + 255) / 256, 256>>>(Wd, 2, OO * DD / 4);
    cvt_kernel<<<(FF * DD / 4 + 255) / 256, 256>>>(W1, 3, FF * DD / 4);
    cvt_kernel<<<(DD * FF / 4 + 255) / 256, 256>>>(W2, 4, DD * FF / 4);

    ln_kernel<<<BL, 256>>>(bv, g1, be1, 0);
    projB_kernel<<<BL, 256>>>(Wb, bb, Wbg, bbg);
    scan_kernel<<<1, 64>>>(h0, A, lasth, write_last);

    {
        dim3 grid(OO / 128, BL / 256);   // (8, 16)
        fused_ssm_t5<<<grid, 256, FUSED_SMEM>>>(bc, bcg, bd, bv);
    }
    ln_kernel<<<BL, 256>>>(bv, g2, be2, 1);

    float *pX3t, *pW1, *pT, *pW2, *pX3;
    cudaGetSymbolAddress((void**)&pX3t, g_x3t);
    cudaGetSymbolAddress((void**)&pW1,  g_W1_t);
    cudaGetSymbolAddress((void**)&pT,   g_t);
    cudaGetSymbolAddress((void**)&pW2,  g_W2_t);
    cudaGetSymbolAddress((void**)&pX3,  g_x3);

    {
        dim3 grid(FF / 128, BL / 256);   // (32, 16)
        gemm_t5<1024, 0><<<grid, 256, GEMM_SMEM>>>(pX3t, pW1, b1, nullptr, pT, FF);
    }
    {
        dim3 grid(DD / 128, BL / 256);   // (8, 16)
        gemm_t5<4096, 1><<<grid, 256, GEMM_SMEM>>>(pT, pW2, b2, pX3, out, DD);
    }
}